// round 3
// baseline (speedup 1.0000x reference)
#include <cuda_runtime.h>

#define N_SRC   100000
#define N_DST   50000
#define N_EDGES 800000
#define DD      64
#define D_OUT   64

// CSR row pointer scratch (static device array — no allocation)
__device__ int g_row_ptr[N_DST + 1];

// ---------------------------------------------------------------------------
// Kernel A: build row_ptr from the sorted dst_idx.
// row_ptr[d] = first edge index with dst >= d;  row_ptr[N_DST] = N_EDGES.
// Every d in [0, N_DST] written exactly once (gap fill at boundaries).
// ---------------------------------------------------------------------------
__global__ void build_row_ptr_kernel(const int* __restrict__ dst_idx) {
    int e = blockIdx.x * blockDim.x + threadIdx.x;
    if (e >= N_EDGES) return;
    int d = dst_idx[e];
    int dprev = (e == 0) ? -1 : dst_idx[e - 1];
    for (int x = dprev + 1; x <= d; ++x) g_row_ptr[x] = e;
    if (e == N_EDGES - 1) {
        for (int x = d + 1; x <= N_DST; ++x) g_row_ptr[x] = N_EDGES;
    }
}

// ---------------------------------------------------------------------------
// Kernel B: fused aggregate(mean) + CV blend + linear + relu.
// Block: 256 threads, 32 dst rows. Static smem only (49152 B), XOR-swizzled
// conflict-free layouts (no padding, no cudaFuncSetAttribute needed).
//
// Phase 1: warp-per-row segmented sum over the CSR edge range (no atomics),
//          CV blend with HBar, write h_neigh, stage x = concat(H_dst, h_neigh)
//          into smem transposed (k-major).
// Phase 2: 32x64 GEMM vs W (k-major in smem), 2x4 register tiles per thread.
// ---------------------------------------------------------------------------
#define TILE_ROWS 32
#define THREADS   256

__global__ __launch_bounds__(THREADS) void sage_fused_kernel(
    const float* __restrict__ H_src,
    const float* __restrict__ H_dst,
    const float* __restrict__ HBar,
    const int*   __restrict__ src_idx,
    const float* __restrict__ W,
    const float* __restrict__ bias,
    float* __restrict__ out_h,
    float* __restrict__ out_hn)
{
    // W transposed: wt[k4][o ^ (k4&7)] holds W[o][4*k4 .. 4*k4+3]   (32768 B)
    __shared__ float4 wt[32][64];
    // X transposed: xt2[k2][row ^ (k2&31)] holds x[row][2*k2 .. 2*k2+1] (16384 B)
    __shared__ float2 xt2[64][32];

    const int tid = threadIdx.x;
    const int rowBase = blockIdx.x * TILE_ROWS;

    // --- load W into smem, transposed + swizzled (coalesced global reads) ---
    const float4* W4 = (const float4*)W;
    for (int i = tid; i < 64 * 32; i += THREADS) {
        int o  = i >> 5;          // 0..63
        int k4 = i & 31;          // 0..31
        wt[k4][o ^ (k4 & 7)] = W4[i];
    }

    // --- Phase 1: aggregation + blend, warp per row ---
    const int warp = tid >> 5;
    const int lane = tid & 31;
    const float2* Hs2 = (const float2*)H_src;

    for (int r = warp; r < TILE_ROWS; r += 8) {
        int row = rowBase + r;
        if (row >= N_DST) continue;

        int start = g_row_ptr[row];
        int end   = g_row_ptr[row + 1];
        int deg   = end - start;

        float2 sum = make_float2(0.f, 0.f);
        int e = start;
        // 4-way unrolled gather for memory-level parallelism
        for (; e + 3 < end; e += 4) {
            int s0 = src_idx[e + 0];
            int s1 = src_idx[e + 1];
            int s2 = src_idx[e + 2];
            int s3 = src_idx[e + 3];
            float2 a0 = Hs2[s0 * 32 + lane];
            float2 a1 = Hs2[s1 * 32 + lane];
            float2 a2 = Hs2[s2 * 32 + lane];
            float2 a3 = Hs2[s3 * 32 + lane];
            sum.x += (a0.x + a1.x) + (a2.x + a3.x);
            sum.y += (a0.y + a1.y) + (a2.y + a3.y);
        }
        for (; e < end; ++e) {
            int s = src_idx[e];
            float2 a = Hs2[s * 32 + lane];
            sum.x += a.x;
            sum.y += a.y;
        }

        float inv = 1.0f / (float)max(deg, 1);
        float2 hb = ((const float2*)HBar )[row * 32 + lane];
        float2 hd = ((const float2*)H_dst)[row * 32 + lane];
        float2 hn;
        hn.x = 0.9f * hb.x + 0.1f * (sum.x * inv);
        hn.y = 0.9f * hb.y + 0.1f * (sum.y * inv);

        // second output: h_neigh (coalesced float2 store)
        ((float2*)out_hn)[row * 32 + lane] = hn;

        // stage concat([H_dst, h_neigh]) transposed: k2 = lane for hd part,
        // k2 = 32 + lane for hn part (x row has 128 dims = 64 float2 chunks)
        int k2a = lane;
        int k2b = 32 + lane;
        xt2[k2a][r ^ (k2a & 31)] = hd;
        xt2[k2b][r ^ (k2b & 31)] = hn;
    }
    __syncthreads();

    // --- Phase 2: GEMM 32 rows x 64 outs, thread tile 2 rows x 4 outs ---
    // tid = rg*16 + cg ; rows 2*rg + i (i=0,1) ; outs cg + 16*j (j=0..3)
    const int rg = tid >> 4;   // 0..15
    const int cg = tid & 15;   // 0..15

    float acc[2][4];
#pragma unroll
    for (int i = 0; i < 2; i++)
#pragma unroll
        for (int j = 0; j < 4; j++) acc[i][j] = 0.f;

#pragma unroll 4
    for (int k4 = 0; k4 < 32; k4++) {
        const int sw = k4 & 7;
        float4 wv[4];
#pragma unroll
        for (int j = 0; j < 4; j++) wv[j] = wt[k4][(cg + 16 * j) ^ sw];

        const int k2a = 2 * k4;
        const int k2b = 2 * k4 + 1;
        float2 xa[2], xb[2];
#pragma unroll
        for (int i = 0; i < 2; i++) {
            int r = 2 * rg + i;
            xa[i] = xt2[k2a][r ^ (k2a & 31)];
            xb[i] = xt2[k2b][r ^ (k2b & 31)];
        }
#pragma unroll
        for (int i = 0; i < 2; i++)
#pragma unroll
            for (int j = 0; j < 4; j++) {
                acc[i][j] += xa[i].x * wv[j].x;
                acc[i][j] += xa[i].y * wv[j].y;
                acc[i][j] += xb[i].x * wv[j].z;
                acc[i][j] += xb[i].y * wv[j].w;
            }
    }

#pragma unroll
    for (int i = 0; i < 2; i++) {
        int row = rowBase + 2 * rg + i;
        if (row < N_DST) {
#pragma unroll
            for (int j = 0; j < 4; j++) {
                int o = cg + 16 * j;
                float v = acc[i][j] + __ldg(&bias[o]);
                out_h[row * 64 + o] = fmaxf(v, 0.0f);
            }
        }
    }
}

// ---------------------------------------------------------------------------
extern "C" void kernel_launch(void* const* d_in, const int* in_sizes, int n_in,
                              void* d_out, int out_size) {
    const float* H_src   = (const float*)d_in[0];
    const float* H_dst   = (const float*)d_in[1];
    const float* HBar    = (const float*)d_in[2];
    const int*   src_idx = (const int*)  d_in[3];
    const int*   dst_idx = (const int*)  d_in[4];
    const float* W       = (const float*)d_in[5];
    const float* bias    = (const float*)d_in[6];

    float* out_h  = (float*)d_out;                       // [N_DST, 64]
    float* out_hn = (float*)d_out + N_DST * D_OUT;       // [N_DST, 64]

    // Kernel A: CSR row_ptr from sorted dst_idx
    build_row_ptr_kernel<<<(N_EDGES + 255) / 256, 256>>>(dst_idx);

    // Kernel B: fused aggregate + blend + linear + relu (static smem only)
    int nblocks = (N_DST + TILE_ROWS - 1) / TILE_ROWS;
    sage_fused_kernel<<<nblocks, THREADS>>>(
        H_src, H_dst, HBar, src_idx, W, bias, out_h, out_hn);
}

// round 5
// speedup vs baseline: 1.0960x; 1.0960x over previous
#include <cuda_runtime.h>

#define N_SRC   100000
#define N_DST   50000
#define N_EDGES 800000
#define DD      64
#define D_OUT   64

// Scratch (static device arrays — no allocation)
__device__ int   g_row_ptr[N_DST + 1];
__device__ float g_wt[128 * 64];          // W transposed: wt[k][o], k-major

// ---------------------------------------------------------------------------
// Kernel A: build row_ptr from the sorted dst_idx.
// ---------------------------------------------------------------------------
__global__ void build_row_ptr_kernel(const int* __restrict__ dst_idx) {
    int e = blockIdx.x * blockDim.x + threadIdx.x;
    if (e >= N_EDGES) return;
    int d = dst_idx[e];
    int dprev = (e == 0) ? -1 : dst_idx[e - 1];
    for (int x = dprev + 1; x <= d; ++x) g_row_ptr[x] = e;
    if (e == N_EDGES - 1) {
        for (int x = d + 1; x <= N_DST; ++x) g_row_ptr[x] = N_EDGES;
    }
}

// ---------------------------------------------------------------------------
// Kernel A2: transpose W [64][128] -> g_wt [128][64] (k-major). 32KB, one-shot.
// ---------------------------------------------------------------------------
__global__ void transpose_w_kernel(const float* __restrict__ W) {
    int t = blockIdx.x * blockDim.x + threadIdx.x;   // 0..8191
    if (t >= 64 * 128) return;
    int o = t >> 7;          // 0..63
    int k = t & 127;         // 0..127
    g_wt[k * 64 + o] = W[o * 128 + k];
}

// ---------------------------------------------------------------------------
// Kernel B: aggregation + CV blend. Warp per dst row, 8-way unrolled gather.
// No smem -> max occupancy. Writes h_neigh only.
// ---------------------------------------------------------------------------
#define AGG_THREADS 256
#define AGG_ROWS    8      // rows per block (one per warp)

__global__ __launch_bounds__(AGG_THREADS) void aggregate_kernel(
    const float* __restrict__ H_src,
    const float* __restrict__ HBar,
    const int*   __restrict__ src_idx,
    float* __restrict__ out_hn)
{
    const int warp = threadIdx.x >> 5;
    const int lane = threadIdx.x & 31;
    const int row  = blockIdx.x * AGG_ROWS + warp;
    if (row >= N_DST) return;

    const int start = g_row_ptr[row];
    const int end   = g_row_ptr[row + 1];
    const int deg   = end - start;

    const float2* Hs2 = (const float2*)H_src;
    float2 hb = ((const float2*)HBar)[row * 32 + lane];   // independent, early

    float2 sum = make_float2(0.f, 0.f);
    int e = start;
    // 8-way unrolled gather: 8 independent loads in flight per warp
    for (; e + 7 < end; e += 8) {
        int s0 = src_idx[e + 0], s1 = src_idx[e + 1];
        int s2 = src_idx[e + 2], s3 = src_idx[e + 3];
        int s4 = src_idx[e + 4], s5 = src_idx[e + 5];
        int s6 = src_idx[e + 6], s7 = src_idx[e + 7];
        float2 a0 = Hs2[s0 * 32 + lane];
        float2 a1 = Hs2[s1 * 32 + lane];
        float2 a2 = Hs2[s2 * 32 + lane];
        float2 a3 = Hs2[s3 * 32 + lane];
        float2 a4 = Hs2[s4 * 32 + lane];
        float2 a5 = Hs2[s5 * 32 + lane];
        float2 a6 = Hs2[s6 * 32 + lane];
        float2 a7 = Hs2[s7 * 32 + lane];
        sum.x += ((a0.x + a1.x) + (a2.x + a3.x)) + ((a4.x + a5.x) + (a6.x + a7.x));
        sum.y += ((a0.y + a1.y) + (a2.y + a3.y)) + ((a4.y + a5.y) + (a6.y + a7.y));
    }
    for (; e + 1 < end; e += 2) {
        int s0 = src_idx[e + 0], s1 = src_idx[e + 1];
        float2 a0 = Hs2[s0 * 32 + lane];
        float2 a1 = Hs2[s1 * 32 + lane];
        sum.x += a0.x + a1.x;
        sum.y += a0.y + a1.y;
    }
    if (e < end) {
        int s = src_idx[e];
        float2 a = Hs2[s * 32 + lane];
        sum.x += a.x;
        sum.y += a.y;
    }

    float inv = 1.0f / (float)max(deg, 1);
    float2 hn;
    hn.x = 0.9f * hb.x + 0.1f * (sum.x * inv);
    hn.y = 0.9f * hb.y + 0.1f * (sum.y * inv);
    ((float2*)out_hn)[row * 32 + lane] = hn;
}

// ---------------------------------------------------------------------------
// Kernel C: GEMM  h = relu([H_dst | h_neigh] @ W^T + b)
// 64 rows x 64 outs per 128-thread block. Thread tile: 8 rows (4 f32x2 pairs)
// x 4 outs, inner product via fma.rn.f32x2 (2x fp32 FMA throughput).
// X staged in 32KB static smem, k-major, swizzle r ^ (k & 56).
// W read from pre-transposed global (L1-resident, 32KB).
// ---------------------------------------------------------------------------
#define G_ROWS    64
#define G_THREADS 128

__device__ __forceinline__ unsigned long long pack2(float v) {
    unsigned long long r;
    asm("mov.b64 %0, {%1, %1};" : "=l"(r) : "f"(v));
    return r;
}
__device__ __forceinline__ void fma2(unsigned long long& d, unsigned long long a,
                                     unsigned long long b) {
    asm("fma.rn.f32x2 %0, %1, %2, %0;" : "+l"(d) : "l"(a), "l"(b));
}

__global__ __launch_bounds__(G_THREADS, 4) void gemm_kernel(
    const float* __restrict__ H_dst,
    const float* __restrict__ hn,
    const float* __restrict__ bias,
    float* __restrict__ out_h)
{
    // xt[k][r ^ (k & 56)] : k-major X tile, 128 k x 64 rows, 32768 B
    __shared__ float xt[128][64];

    const int tid = threadIdx.x;
    const int rowBase = blockIdx.x * G_ROWS;

    // --- stage X: k < 64 from H_dst, k >= 64 from hn (coalesced reads) ---
    // 64 rows x 16 float4 chunks per source. i -> (r, c4).
    for (int i = tid; i < 64 * 16; i += G_THREADS) {
        int r  = i >> 4;
        int c4 = i & 15;
        int row = rowBase + r;
        float4 vd = make_float4(0.f, 0.f, 0.f, 0.f);
        float4 vn = make_float4(0.f, 0.f, 0.f, 0.f);
        if (row < N_DST) {
            vd = ((const float4*)H_dst)[row * 16 + c4];
            vn = ((const float4*)hn)   [row * 16 + c4];
        }
        int k0 = 4 * c4;
        xt[k0 + 0][r ^ ((k0 + 0) & 56)] = vd.x;
        xt[k0 + 1][r ^ ((k0 + 1) & 56)] = vd.y;
        xt[k0 + 2][r ^ ((k0 + 2) & 56)] = vd.z;
        xt[k0 + 3][r ^ ((k0 + 3) & 56)] = vd.w;
        int k1 = 64 + 4 * c4;
        xt[k1 + 0][r ^ ((k1 + 0) & 56)] = vn.x;
        xt[k1 + 1][r ^ ((k1 + 1) & 56)] = vn.y;
        xt[k1 + 2][r ^ ((k1 + 2) & 56)] = vn.z;
        xt[k1 + 3][r ^ ((k1 + 3) & 56)] = vn.w;
    }
    __syncthreads();

    // --- mainloop: 4 row-pairs x 4 outs per thread, f32x2 FMAs ---
    const int rg = tid >> 4;     // 0..7  -> rows 8*rg .. 8*rg+7
    const int cg = tid & 15;     // 0..15 -> outs 4*cg .. 4*cg+3

    unsigned long long acc[4][4];
#pragma unroll
    for (int p = 0; p < 4; p++)
#pragma unroll
        for (int j = 0; j < 4; j++) acc[p][j] = 0ULL;

    const float4* wt4 = (const float4*)g_wt;

#pragma unroll 4
    for (int k = 0; k < 128; k++) {
        const int sw = k & 56;
        unsigned long long xv[4];
#pragma unroll
        for (int p = 0; p < 4; p++) {
            // rows 8rg+2p, 8rg+2p+1 are adjacent in xt -> one 8B load
            xv[p] = *(const unsigned long long*)&xt[k][(8 * rg + 2 * p) ^ sw];
        }
        float4 wv = __ldg(&wt4[k * 16 + cg]);
        unsigned long long w0 = pack2(wv.x);
        unsigned long long w1 = pack2(wv.y);
        unsigned long long w2 = pack2(wv.z);
        unsigned long long w3 = pack2(wv.w);
#pragma unroll
        for (int p = 0; p < 4; p++) {
            fma2(acc[p][0], xv[p], w0);
            fma2(acc[p][1], xv[p], w1);
            fma2(acc[p][2], xv[p], w2);
            fma2(acc[p][3], xv[p], w3);
        }
    }

    // --- epilogue: bias + relu, float4 stores (row-coalesced across cg) ---
    float4 bv = __ldg(&((const float4*)bias)[cg]);
#pragma unroll
    for (int p = 0; p < 4; p++) {
        float lo[4], hi[4];
#pragma unroll
        for (int j = 0; j < 4; j++) {
            float l, h;
            asm("mov.b64 {%0, %1}, %2;" : "=f"(l), "=f"(h) : "l"(acc[p][j]));
            lo[j] = l; hi[j] = h;
        }
        int r0 = rowBase + 8 * rg + 2 * p;
        if (r0 < N_DST) {
            float4 v;
            v.x = fmaxf(lo[0] + bv.x, 0.f);
            v.y = fmaxf(lo[1] + bv.y, 0.f);
            v.z = fmaxf(lo[2] + bv.z, 0.f);
            v.w = fmaxf(lo[3] + bv.w, 0.f);
            ((float4*)out_h)[r0 * 16 + cg] = v;
        }
        if (r0 + 1 < N_DST) {
            float4 v;
            v.x = fmaxf(hi[0] + bv.x, 0.f);
            v.y = fmaxf(hi[1] + bv.y, 0.f);
            v.z = fmaxf(hi[2] + bv.z, 0.f);
            v.w = fmaxf(hi[3] + bv.w, 0.f);
            ((float4*)out_h)[(r0 + 1) * 16 + cg] = v;
        }
    }
}

// ---------------------------------------------------------------------------
extern "C" void kernel_launch(void* const* d_in, const int* in_sizes, int n_in,
                              void* d_out, int out_size) {
    const float* H_src   = (const float*)d_in[0];
    const float* H_dst   = (const float*)d_in[1];
    const float* HBar    = (const float*)d_in[2];
    const int*   src_idx = (const int*)  d_in[3];
    const int*   dst_idx = (const int*)  d_in[4];
    const float* W       = (const float*)d_in[5];
    const float* bias    = (const float*)d_in[6];

    float* out_h  = (float*)d_out;                       // [N_DST, 64]
    float* out_hn = (float*)d_out + N_DST * D_OUT;       // [N_DST, 64]

    build_row_ptr_kernel<<<(N_EDGES + 255) / 256, 256>>>(dst_idx);
    transpose_w_kernel<<<(64 * 128 + 255) / 256, 256>>>(W);

    aggregate_kernel<<<(N_DST + AGG_ROWS - 1) / AGG_ROWS, AGG_THREADS>>>(
        H_src, HBar, src_idx, out_hn);

    gemm_kernel<<<(N_DST + G_ROWS - 1) / G_ROWS, G_THREADS>>>(
        H_dst, out_hn, bias, out_h);
}

// round 6
// speedup vs baseline: 1.1779x; 1.0747x over previous
#include <cuda_runtime.h>

#define N_SRC   100000
#define N_DST   50000
#define N_EDGES 800000
#define DD      64
#define D_OUT   64

// Scratch (static device arrays — no allocation)
__device__ int   g_row_ptr[N_DST + 1];
__device__ float g_wt[128 * 64];          // W transposed: wt[k][o], k-major

// ---------------------------------------------------------------------------
// Kernel A: build row_ptr from the sorted dst_idx.
// ---------------------------------------------------------------------------
__global__ void build_row_ptr_kernel(const int* __restrict__ dst_idx) {
    int e = blockIdx.x * blockDim.x + threadIdx.x;
    if (e >= N_EDGES) return;
    int d = dst_idx[e];
    int dprev = (e == 0) ? -1 : dst_idx[e - 1];
    for (int x = dprev + 1; x <= d; ++x) g_row_ptr[x] = e;
    if (e == N_EDGES - 1) {
        for (int x = d + 1; x <= N_DST; ++x) g_row_ptr[x] = N_EDGES;
    }
}

// ---------------------------------------------------------------------------
// Kernel A2: transpose W [64][128] -> g_wt [128][64] (k-major). 32KB, one-shot.
// ---------------------------------------------------------------------------
__global__ void transpose_w_kernel(const float* __restrict__ W) {
    int t = blockIdx.x * blockDim.x + threadIdx.x;   // 0..8191
    if (t >= 64 * 128) return;
    int o = t >> 7;          // 0..63
    int k = t & 127;         // 0..127
    g_wt[k * 64 + o] = W[o * 128 + k];
}

// ---------------------------------------------------------------------------
// Kernel B: aggregation + CV blend. Warp per dst row, 8-way unrolled gather.
// No smem -> max occupancy. Writes h_neigh only.
// ---------------------------------------------------------------------------
#define AGG_THREADS 256
#define AGG_ROWS    8      // rows per block (one per warp)

__global__ __launch_bounds__(AGG_THREADS) void aggregate_kernel(
    const float* __restrict__ H_src,
    const float* __restrict__ HBar,
    const int*   __restrict__ src_idx,
    float* __restrict__ out_hn)
{
    const int warp = threadIdx.x >> 5;
    const int lane = threadIdx.x & 31;
    const int row  = blockIdx.x * AGG_ROWS + warp;
    if (row >= N_DST) return;

    const int start = g_row_ptr[row];
    const int end   = g_row_ptr[row + 1];
    const int deg   = end - start;

    const float2* Hs2 = (const float2*)H_src;
    float2 hb = ((const float2*)HBar)[row * 32 + lane];   // independent, early

    float2 sum = make_float2(0.f, 0.f);
    int e = start;
    // 8-way unrolled gather: 8 independent loads in flight per warp
    for (; e + 7 < end; e += 8) {
        int s0 = src_idx[e + 0], s1 = src_idx[e + 1];
        int s2 = src_idx[e + 2], s3 = src_idx[e + 3];
        int s4 = src_idx[e + 4], s5 = src_idx[e + 5];
        int s6 = src_idx[e + 6], s7 = src_idx[e + 7];
        float2 a0 = Hs2[s0 * 32 + lane];
        float2 a1 = Hs2[s1 * 32 + lane];
        float2 a2 = Hs2[s2 * 32 + lane];
        float2 a3 = Hs2[s3 * 32 + lane];
        float2 a4 = Hs2[s4 * 32 + lane];
        float2 a5 = Hs2[s5 * 32 + lane];
        float2 a6 = Hs2[s6 * 32 + lane];
        float2 a7 = Hs2[s7 * 32 + lane];
        sum.x += ((a0.x + a1.x) + (a2.x + a3.x)) + ((a4.x + a5.x) + (a6.x + a7.x));
        sum.y += ((a0.y + a1.y) + (a2.y + a3.y)) + ((a4.y + a5.y) + (a6.y + a7.y));
    }
    for (; e + 1 < end; e += 2) {
        int s0 = src_idx[e + 0], s1 = src_idx[e + 1];
        float2 a0 = Hs2[s0 * 32 + lane];
        float2 a1 = Hs2[s1 * 32 + lane];
        sum.x += a0.x + a1.x;
        sum.y += a0.y + a1.y;
    }
    if (e < end) {
        int s = src_idx[e];
        float2 a = Hs2[s * 32 + lane];
        sum.x += a.x;
        sum.y += a.y;
    }

    float inv = 1.0f / (float)max(deg, 1);
    float2 hn;
    hn.x = 0.9f * hb.x + 0.1f * (sum.x * inv);
    hn.y = 0.9f * hb.y + 0.1f * (sum.y * inv);
    ((float2*)out_hn)[row * 32 + lane] = hn;
}

// ---------------------------------------------------------------------------
// Kernel C: GEMM  h = relu([H_dst | h_neigh] @ W^T + b)
// 64 rows x 64 outs per 256-thread block. Thread tile: 4 rows (2 f32x2 pairs)
// x 4 outs. Per-k: 1 LDS.128 (4 rows of x) + 1 LDG.128 (W, L1-hot) + 4 packs
// + 8 fma.rn.f32x2. 50% occupancy target (32 warps/SM) to hide load latency.
// X staged in 32KB static smem, k-major, swizzle r ^ (k & 56).
// ---------------------------------------------------------------------------
#define G_ROWS    64
#define G_THREADS 256

__device__ __forceinline__ unsigned long long pack2(float v) {
    unsigned long long r;
    asm("mov.b64 %0, {%1, %1};" : "=l"(r) : "f"(v));
    return r;
}
__device__ __forceinline__ void fma2(unsigned long long& d, unsigned long long a,
                                     unsigned long long b) {
    asm("fma.rn.f32x2 %0, %1, %2, %0;" : "+l"(d) : "l"(a), "l"(b));
}

__global__ __launch_bounds__(G_THREADS, 4) void gemm_kernel(
    const float* __restrict__ H_dst,
    const float* __restrict__ hn,
    const float* __restrict__ bias,
    float* __restrict__ out_h)
{
    // xt[k][r ^ (k & 56)] : k-major X tile, 128 k x 64 rows, 32768 B
    __shared__ float xt[128][64];

    const int tid = threadIdx.x;
    const int rowBase = blockIdx.x * G_ROWS;

    // --- stage X: k < 64 from H_dst, k >= 64 from hn (coalesced reads) ---
    // 64 rows x 16 float4 chunks per source; 256 threads -> 4 iterations.
    for (int i = tid; i < 64 * 16; i += G_THREADS) {
        int r  = i >> 4;
        int c4 = i & 15;
        int row = rowBase + r;
        float4 vd = make_float4(0.f, 0.f, 0.f, 0.f);
        float4 vn = make_float4(0.f, 0.f, 0.f, 0.f);
        if (row < N_DST) {
            vd = ((const float4*)H_dst)[row * 16 + c4];
            vn = ((const float4*)hn)   [row * 16 + c4];
        }
        int k0 = 4 * c4;
        xt[k0 + 0][r ^ ((k0 + 0) & 56)] = vd.x;
        xt[k0 + 1][r ^ ((k0 + 1) & 56)] = vd.y;
        xt[k0 + 2][r ^ ((k0 + 2) & 56)] = vd.z;
        xt[k0 + 3][r ^ ((k0 + 3) & 56)] = vd.w;
        int k1 = 64 + 4 * c4;
        xt[k1 + 0][r ^ ((k1 + 0) & 56)] = vn.x;
        xt[k1 + 1][r ^ ((k1 + 1) & 56)] = vn.y;
        xt[k1 + 2][r ^ ((k1 + 2) & 56)] = vn.z;
        xt[k1 + 3][r ^ ((k1 + 3) & 56)] = vn.w;
    }
    __syncthreads();

    // --- mainloop: 2 row-pairs x 4 outs per thread, f32x2 FMAs ---
    const int rg = tid >> 4;     // 0..15 -> rows 4*rg .. 4*rg+3
    const int cg = tid & 15;     // 0..15 -> outs 4*cg .. 4*cg+3

    unsigned long long acc[2][4];
#pragma unroll
    for (int p = 0; p < 2; p++)
#pragma unroll
        for (int j = 0; j < 4; j++) acc[p][j] = 0ULL;

    const float4* wt4 = (const float4*)g_wt;

#pragma unroll 8
    for (int k = 0; k < 128; k++) {
        const int sw = k & 56;
        // 4 consecutive rows of x: one 16B LDS (4rg is 4-aligned; sw flips
        // only bits 3-5, so (4rg)^sw stays 4-aligned and rows stay contiguous)
        float4 xq = *(const float4*)&xt[k][(4 * rg) ^ sw];
        unsigned long long xv0, xv1;
        asm("mov.b64 %0, {%1, %2};" : "=l"(xv0) : "f"(xq.x), "f"(xq.y));
        asm("mov.b64 %0, {%1, %2};" : "=l"(xv1) : "f"(xq.z), "f"(xq.w));

        float4 wv = __ldg(&wt4[k * 16 + cg]);
        unsigned long long w0 = pack2(wv.x);
        unsigned long long w1 = pack2(wv.y);
        unsigned long long w2 = pack2(wv.z);
        unsigned long long w3 = pack2(wv.w);

        fma2(acc[0][0], xv0, w0);
        fma2(acc[0][1], xv0, w1);
        fma2(acc[0][2], xv0, w2);
        fma2(acc[0][3], xv0, w3);
        fma2(acc[1][0], xv1, w0);
        fma2(acc[1][1], xv1, w1);
        fma2(acc[1][2], xv1, w2);
        fma2(acc[1][3], xv1, w3);
    }

    // --- epilogue: bias + relu, float4 stores (row-coalesced across cg) ---
    float4 bv = __ldg(&((const float4*)bias)[cg]);
#pragma unroll
    for (int p = 0; p < 2; p++) {
        float lo[4], hi[4];
#pragma unroll
        for (int j = 0; j < 4; j++) {
            float l, h;
            asm("mov.b64 {%0, %1}, %2;" : "=f"(l), "=f"(h) : "l"(acc[p][j]));
            lo[j] = l; hi[j] = h;
        }
        int r0 = rowBase + 4 * rg + 2 * p;
        if (r0 < N_DST) {
            float4 v;
            v.x = fmaxf(lo[0] + bv.x, 0.f);
            v.y = fmaxf(lo[1] + bv.y, 0.f);
            v.z = fmaxf(lo[2] + bv.z, 0.f);
            v.w = fmaxf(lo[3] + bv.w, 0.f);
            ((float4*)out_h)[r0 * 16 + cg] = v;
        }
        if (r0 + 1 < N_DST) {
            float4 v;
            v.x = fmaxf(hi[0] + bv.x, 0.f);
            v.y = fmaxf(hi[1] + bv.y, 0.f);
            v.z = fmaxf(hi[2] + bv.z, 0.f);
            v.w = fmaxf(hi[3] + bv.w, 0.f);
            ((float4*)out_h)[(r0 + 1) * 16 + cg] = v;
        }
    }
}

// ---------------------------------------------------------------------------
extern "C" void kernel_launch(void* const* d_in, const int* in_sizes, int n_in,
                              void* d_out, int out_size) {
    const float* H_src   = (const float*)d_in[0];
    const float* H_dst   = (const float*)d_in[1];
    const float* HBar    = (const float*)d_in[2];
    const int*   src_idx = (const int*)  d_in[3];
    const int*   dst_idx = (const int*)  d_in[4];
    const float* W       = (const float*)d_in[5];
    const float* bias    = (const float*)d_in[6];

    float* out_h  = (float*)d_out;                       // [N_DST, 64]
    float* out_hn = (float*)d_out + N_DST * D_OUT;       // [N_DST, 64]

    build_row_ptr_kernel<<<(N_EDGES + 255) / 256, 256>>>(dst_idx);
    transpose_w_kernel<<<(64 * 128 + 255) / 256, 256>>>(W);

    aggregate_kernel<<<(N_DST + AGG_ROWS - 1) / AGG_ROWS, AGG_THREADS>>>(
        H_src, HBar, src_idx, out_hn);

    gemm_kernel<<<(N_DST + G_ROWS - 1) / G_ROWS, G_THREADS>>>(
        H_dst, out_hn, bias, out_h);
}